// round 4
// baseline (speedup 1.0000x reference)
#include <cuda_runtime.h>
#include <cstdint>

// out[b,co,h,w] = sum_{kh,kw,cin} xpad[b,cin,h+kh-1,w+kw-1] * (exp(k[kh,kw,cin,co]+5) - delta_w)
//              + sum_r exp(k_r+5) - delta_x * sum_r k_r + bias[co]
// Derivation: alpha=1 so exp(lse) = sum exp(z); exp(log(x+1)) = x+1; padded
// positions of lnx are 0 -> exp(0)=1, identical to x=0 in the (x+1) form.
// The -xp*delta_w term is an all-ones conv of x, folded into W'' = e - delta_w.

#define B_     8
#define CIN_   32
#define H_     28
#define W_     28
#define COUT_  64
#define R_     288   // 3*3*32

constexpr int TR   = 7;    // output rows per block (4 tiles cover 28)
constexpr int CG   = 8;    // couts per block (8 groups cover 64)
constexpr int NTHR = 224;  // 7 warps: warp = row, lanes 0..27 = cols

__global__ void __launch_bounds__(NTHR) fused_conv_kernel(
    const float* __restrict__ x,
    const float* __restrict__ k,
    const float* __restrict__ bias,
    const float* __restrict__ dxp,
    const float* __restrict__ dwp,
    float* __restrict__ out)
{
    __shared__ __align__(16) float sW[R_ * CG];        // 9216 B  [r][co_local]
    __shared__ float sX[CIN_ * 9 * 32];                // 36864 B [cin][9 rows][32 cols]
    __shared__ float redE[CG][28];
    __shared__ float redK[CG][28];
    __shared__ float sC[CG];

    const int tid    = threadIdx.x;
    const int rt     = blockIdx.x;          // 0..3 row tile
    const int b      = blockIdx.y;          // 0..7 batch
    const int cg     = blockIdx.z;          // 0..7 cout group
    const int row0   = rt * TR;
    const int cobase = cg * CG;

    const float dw = dwp[0];
    const float dx = dxp[0];

    // ---- Phase 1a: weight transform (exp) + partial sums for C[co] ----
    {
        const int co   = tid & 7;           // 0..7 local cout
        const int base = tid >> 3;          // 0..27
        float se = 0.f, sk = 0.f;
        for (int rr = base; rr < R_; rr += 28) {
            float kv = k[rr * COUT_ + cobase + co];
            float e  = expf(kv + 5.0f);
            sW[rr * CG + co] = e - dw;
            se += e;
            sk += kv;
        }
        redE[co][base] = se;
        redK[co][base] = sk;
    }

    // ---- Phase 1b: input tile, rows row0-1..row0+7, cols -1..30, zero pad ----
    {
        const float* xb = x + (size_t)b * (CIN_ * H_ * W_);
        for (int idx = tid; idx < CIN_ * 9 * 32; idx += NTHR) {
            int c   = idx / 288;
            int rem = idx - c * 288;
            int rr  = rem >> 5;             // 0..8
            int cc  = rem & 31;             // 0..31
            int ir  = row0 - 1 + rr;
            int ic  = cc - 1;
            float v = 0.f;
            if ((unsigned)ir < (unsigned)H_ && (unsigned)ic < (unsigned)W_)
                v = xb[(c * H_ + ir) * W_ + ic];
            sX[idx] = v;
        }
    }
    __syncthreads();

    // ---- Phase 1c: finish C[co] reduction ----
    if (tid < CG) {
        float S = 0.f, K = 0.f;
        #pragma unroll
        for (int i = 0; i < 28; i++) { S += redE[tid][i]; K += redK[tid][i]; }
        sC[tid] = S - dx * K + bias[cobase + tid];
    }
    __syncthreads();

    // ---- Phase 2: main conv, one pixel per thread, 8 couts in f32x2 accs ----
    const int warp = tid >> 5;              // output row within tile
    const int lane = tid & 31;              // output col (valid < 28)
    if (lane < 28) {
        unsigned long long a0 = 0ull, a1 = 0ull, a2 = 0ull, a3 = 0ull;

        #pragma unroll 1
        for (int kh = 0; kh < 3; kh++) {
            #pragma unroll 1
            for (int kw = 0; kw < 3; kw++) {
                const float* xp = &sX[(warp + kh) * 32 + (lane + kw)];
                const float* wp = &sW[((kh * 3 + kw) * CIN_) * CG];
                #pragma unroll
                for (int c = 0; c < CIN_; c++) {
                    uint32_t xu = __float_as_uint(xp[c * 288]);
                    unsigned long long xv2;
                    asm("mov.b64 %0, {%1, %1};" : "=l"(xv2) : "r"(xu));
                    ulonglong2 wA = *reinterpret_cast<const ulonglong2*>(wp + c * CG);
                    ulonglong2 wB = *reinterpret_cast<const ulonglong2*>(wp + c * CG + 4);
                    asm("fma.rn.f32x2 %0, %1, %2, %3;" : "=l"(a0) : "l"(xv2), "l"(wA.x), "l"(a0));
                    asm("fma.rn.f32x2 %0, %1, %2, %3;" : "=l"(a1) : "l"(xv2), "l"(wA.y), "l"(a1));
                    asm("fma.rn.f32x2 %0, %1, %2, %3;" : "=l"(a2) : "l"(xv2), "l"(wB.x), "l"(a2));
                    asm("fma.rn.f32x2 %0, %1, %2, %3;" : "=l"(a3) : "l"(xv2), "l"(wB.y), "l"(a3));
                }
            }
        }

        float res[8];
        res[0] = __uint_as_float((uint32_t)(a0      )) + sC[0];
        res[1] = __uint_as_float((uint32_t)(a0 >> 32)) + sC[1];
        res[2] = __uint_as_float((uint32_t)(a1      )) + sC[2];
        res[3] = __uint_as_float((uint32_t)(a1 >> 32)) + sC[3];
        res[4] = __uint_as_float((uint32_t)(a2      )) + sC[4];
        res[5] = __uint_as_float((uint32_t)(a2 >> 32)) + sC[5];
        res[6] = __uint_as_float((uint32_t)(a3      )) + sC[6];
        res[7] = __uint_as_float((uint32_t)(a3 >> 32)) + sC[7];

        const int row = row0 + warp;
        float* o = out + (((size_t)b * COUT_ + cobase) * H_ + row) * W_ + lane;
        #pragma unroll
        for (int j = 0; j < 8; j++)
            o[(size_t)j * (H_ * W_)] = res[j];
    }
}

extern "C" void kernel_launch(void* const* d_in, const int* in_sizes, int n_in,
                              void* d_out, int out_size)
{
    (void)in_sizes; (void)n_in; (void)out_size;
    const float* x    = (const float*)d_in[0];
    const float* k    = (const float*)d_in[1];
    const float* bias = (const float*)d_in[2];
    const float* dx   = (const float*)d_in[3];
    const float* dw   = (const float*)d_in[4];
    float* out        = (float*)d_out;

    dim3 grid(4, B_, COUT_ / CG);   // (row tiles, batch, cout groups) = 4*8*8 = 256
    fused_conv_kernel<<<grid, NTHR>>>(x, k, bias, dx, dw, out);
}

// round 5
// speedup vs baseline: 1.1254x; 1.1254x over previous
#include <cuda_runtime.h>
#include <cstdint>

// out[b,co,h,w] = sum_{kh,kw,cin} xpad[b,cin,h+kh-1,w+kw-1] * (exp(k[kh,kw,cin,co]+5) - delta_w)
//              + sum_r exp(k_r+5) - delta_x * sum_r k_r + bias[co]
// alpha=1 so exp(lse) = sum exp(z); exp(log(x+1)) = x+1; zero-padded lnx
// positions give exp(0)=1 == the (x+1) form at x=0. The -xp*delta_w term is
// an all-ones conv of x folded into W'' = e - delta_w.

#define B_     8
#define CIN_   32
#define H_     28
#define W_     28
#define COUT_  64
#define R_     288   // 3*3*32

constexpr int TR   = 4;    // output rows per block (7 tiles cover 28)
constexpr int CG   = 8;    // couts per block (8 groups cover 64)
constexpr int NTHR = 128;  // 4 warps: warp = row, lanes 0..27 = cols
constexpr int XR   = TR + 2;              // 6 input rows
constexpr int XSZ  = CIN_ * XR * 32;      // 6144 floats

__global__ void __launch_bounds__(NTHR) fused_conv_kernel(
    const float* __restrict__ x,
    const float* __restrict__ k,
    const float* __restrict__ bias,
    const float* __restrict__ dxp,
    const float* __restrict__ dwp,
    float* __restrict__ out)
{
    __shared__ __align__(16) float sW[R_ * CG];   // 9216 B  [r][co_local]
    __shared__ float sX[XSZ];                     // 24576 B [cin][6 rows][32 cols]
    __shared__ float redE[CG][16];
    __shared__ float redK[CG][16];
    __shared__ float sC[CG];

    const int tid    = threadIdx.x;
    const int rt     = blockIdx.x;          // 0..6 row tile
    const int b      = blockIdx.y;          // 0..7 batch
    const int cg     = blockIdx.z;          // 0..7 cout group
    const int row0   = rt * TR;
    const int cobase = cg * CG;

    const float dw = dwp[0];
    const float dx = dxp[0];

    // ---- Phase 1a: weight transform (exp) + partial sums for C[co] ----
    {
        const int co  = tid & 7;            // 0..7 local cout
        const int seg = tid >> 3;           // 0..15
        float se = 0.f, sk = 0.f;
        #pragma unroll
        for (int rr = seg; rr < R_; rr += 16) {
            float kv = k[rr * COUT_ + cobase + co];
            float e  = expf(kv + 5.0f);
            sW[rr * CG + co] = e - dw;
            se += e;
            sk += kv;
        }
        redE[co][seg] = se;
        redK[co][seg] = sk;
    }

    // ---- Phase 1b: input tile, rows row0-1..row0+4, cols -1..30, zero pad ----
    {
        const float* xb = x + (size_t)b * (CIN_ * H_ * W_);
        #pragma unroll 4
        for (int idx = tid; idx < XSZ; idx += NTHR) {
            int c   = idx / (XR * 32);
            int rem = idx - c * (XR * 32);
            int rr  = rem >> 5;             // 0..5
            int cc  = rem & 31;             // 0..31
            int ir  = row0 - 1 + rr;
            int ic  = cc - 1;
            float v = 0.f;
            if ((unsigned)ir < (unsigned)H_ && (unsigned)ic < (unsigned)W_)
                v = xb[(c * H_ + ir) * W_ + ic];
            sX[idx] = v;
        }
    }
    __syncthreads();

    // ---- Phase 1c: finish C[co] reduction ----
    if (tid < CG) {
        float S = 0.f, K = 0.f;
        #pragma unroll
        for (int i = 0; i < 16; i++) { S += redE[tid][i]; K += redK[tid][i]; }
        sC[tid] = S - dx * K + bias[cobase + tid];
    }
    __syncthreads();

    // ---- Phase 2: main conv, one pixel per thread, 8 couts in f32x2 accs ----
    const int warp = tid >> 5;              // output row within tile (0..3)
    const int lane = tid & 31;              // output col (valid < 28)
    if (lane < 28) {
        unsigned long long a0 = 0ull, a1 = 0ull, a2 = 0ull, a3 = 0ull;

        #pragma unroll 1
        for (int kh = 0; kh < 3; kh++) {
            #pragma unroll 1
            for (int kw = 0; kw < 3; kw++) {
                const float* xp = &sX[(warp + kh) * 32 + (lane + kw)];
                const float* wp = &sW[((kh * 3 + kw) * CIN_) * CG];
                #pragma unroll
                for (int c = 0; c < CIN_; c++) {
                    uint32_t xu = __float_as_uint(xp[c * (XR * 32)]);
                    unsigned long long xv2;
                    asm("mov.b64 %0, {%1, %1};" : "=l"(xv2) : "r"(xu));
                    ulonglong2 wA = *reinterpret_cast<const ulonglong2*>(wp + c * CG);
                    ulonglong2 wB = *reinterpret_cast<const ulonglong2*>(wp + c * CG + 4);
                    asm("fma.rn.f32x2 %0, %1, %2, %3;" : "=l"(a0) : "l"(xv2), "l"(wA.x), "l"(a0));
                    asm("fma.rn.f32x2 %0, %1, %2, %3;" : "=l"(a1) : "l"(xv2), "l"(wA.y), "l"(a1));
                    asm("fma.rn.f32x2 %0, %1, %2, %3;" : "=l"(a2) : "l"(xv2), "l"(wB.x), "l"(a2));
                    asm("fma.rn.f32x2 %0, %1, %2, %3;" : "=l"(a3) : "l"(xv2), "l"(wB.y), "l"(a3));
                }
            }
        }

        float res[8];
        res[0] = __uint_as_float((uint32_t)(a0      )) + sC[0];
        res[1] = __uint_as_float((uint32_t)(a0 >> 32)) + sC[1];
        res[2] = __uint_as_float((uint32_t)(a1      )) + sC[2];
        res[3] = __uint_as_float((uint32_t)(a1 >> 32)) + sC[3];
        res[4] = __uint_as_float((uint32_t)(a2      )) + sC[4];
        res[5] = __uint_as_float((uint32_t)(a2 >> 32)) + sC[5];
        res[6] = __uint_as_float((uint32_t)(a3      )) + sC[6];
        res[7] = __uint_as_float((uint32_t)(a3 >> 32)) + sC[7];

        const int row = row0 + warp;
        float* o = out + (((size_t)b * COUT_ + cobase) * H_ + row) * W_ + lane;
        #pragma unroll
        for (int j = 0; j < 8; j++)
            o[(size_t)j * (H_ * W_)] = res[j];
    }
}

extern "C" void kernel_launch(void* const* d_in, const int* in_sizes, int n_in,
                              void* d_out, int out_size)
{
    (void)in_sizes; (void)n_in; (void)out_size;
    const float* x    = (const float*)d_in[0];
    const float* k    = (const float*)d_in[1];
    const float* bias = (const float*)d_in[2];
    const float* dx   = (const float*)d_in[3];
    const float* dw   = (const float*)d_in[4];
    float* out        = (float*)d_out;

    dim3 grid(7, B_, COUT_ / CG);   // (row tiles, batch, cout groups) = 7*8*8 = 448
    fused_conv_kernel<<<grid, NTHR>>>(x, k, bias, dx, dw, out);
}

// round 6
// speedup vs baseline: 1.2429x; 1.1044x over previous
#include <cuda_runtime.h>
#include <cstdint>

// out[b,co,h,w] = sum_{kh,kw,cin} xpad[b,cin,h+kh-1,w+kw-1] * (exp(k[kh,kw,cin,co]+5) - delta_w)
//              + sum_r exp(k_r+5) - delta_x * sum_r k_r + bias[co]
// alpha=1 so exp(lse) = sum exp(z); exp(log(x+1)) = x+1; zero-padded lnx
// positions give exp(0)=1 == the (x+1) form at x=0. The -xp*delta_w term is
// an all-ones conv of x folded into W'' = e - delta_w.

#define B_     8
#define CIN_   32
#define H_     28
#define W_     28
#define COUT_  64
#define R_     288   // 3*3*32

constexpr int TR   = 2;    // output rows per block (14 tiles cover 28)
constexpr int CG   = 8;    // couts per block
constexpr int NTHR = 128;  // 4 warps; warps 0,1: rows 0,1 cin[0,16); warps 2,3: rows 0,1 cin[16,32)
constexpr int XR   = TR + 2;              // 4 input rows
constexpr int XSZ  = CIN_ * XR * 32;      // 4096 floats = 16 KB

__global__ void __launch_bounds__(NTHR, 6) fused_conv_kernel(
    const float* __restrict__ x,
    const float* __restrict__ k,
    const float* __restrict__ bias,
    const float* __restrict__ dxp,
    const float* __restrict__ dwp,
    float* __restrict__ out)
{
    __shared__ __align__(16) float sW[R_ * CG];   // 9216 B  [r][co_local]
    __shared__ __align__(16) float sX[XSZ];       // 16384 B [cin][4 rows][32 cols]
    __shared__ __align__(16) float sP[TR * 28 * CG]; // 7168 B partials from cin-half 1
    __shared__ float redE[CG][16];
    __shared__ float redK[CG][16];
    __shared__ float sC[CG];

    const int tid    = threadIdx.x;
    const int rt     = blockIdx.x;          // 0..13 row tile
    const int b      = blockIdx.y;          // 0..7 batch
    const int cg     = blockIdx.z;          // 0..7 cout group
    const int row0   = rt * TR;
    const int cobase = cg * CG;

    const float dw = dwp[0];
    const float dx = dxp[0];

    // ---- Phase 1a: weight transform (exp) + partial sums for C[co] ----
    {
        const int co  = tid & 7;            // 0..7 local cout
        const int seg = tid >> 3;           // 0..15
        float se = 0.f, sk = 0.f;
        #pragma unroll
        for (int rr = seg; rr < R_; rr += 16) {
            float kv = k[rr * COUT_ + cobase + co];
            float e  = expf(kv + 5.0f);
            sW[rr * CG + co] = e - dw;
            se += e;
            sk += kv;
        }
        redE[co][seg] = se;
        redK[co][seg] = sk;
    }

    // ---- Phase 1b: input tile, rows row0-1..row0+2, cols -1..30, zero pad ----
    {
        const float* xb = x + (size_t)b * (CIN_ * H_ * W_);
        #pragma unroll
        for (int i = 0; i < XSZ / NTHR; i++) {
            int idx = i * NTHR + tid;
            int c   = idx >> 7;             // /128
            int rem = idx & 127;
            int rr  = rem >> 5;             // 0..3
            int cc  = rem & 31;             // 0..31
            int ir  = row0 - 1 + rr;
            int ic  = cc - 1;
            float v = 0.f;
            if ((unsigned)ir < (unsigned)H_ && (unsigned)ic < (unsigned)W_)
                v = xb[(c * H_ + ir) * W_ + ic];
            sX[idx] = v;
        }
    }

    // ---- Phase 1c: finish C[co] reduction ----
    __syncthreads();
    if (tid < CG) {
        float S = 0.f, K = 0.f;
        #pragma unroll
        for (int i = 0; i < 16; i++) { S += redE[tid][i]; K += redK[tid][i]; }
        sC[tid] = S - dx * K + bias[cobase + tid];
    }
    __syncthreads();

    // ---- Phase 2: main conv. warp -> (row, cin-half); lane -> col ----
    const int wid   = tid >> 5;
    const int lane  = tid & 31;
    const int rowL  = wid & 1;              // local output row 0/1
    const int chalf = wid >> 1;             // 0: cin 0..15, 1: cin 16..31
    const int c0    = chalf * 16;

    unsigned long long a0 = 0ull, a1 = 0ull, a2 = 0ull, a3 = 0ull;

    if (lane < 28) {
        #pragma unroll 1
        for (int kh = 0; kh < 3; kh++) {
            #pragma unroll 1
            for (int kw = 0; kw < 3; kw++) {
                const float* xp = &sX[c0 * (XR * 32) + (rowL + kh) * 32 + (lane + kw)];
                const float* wp = &sW[((kh * 3 + kw) * CIN_ + c0) * CG];
                #pragma unroll
                for (int c = 0; c < 16; c++) {
                    uint32_t xu = __float_as_uint(xp[c * (XR * 32)]);
                    unsigned long long xv2;
                    asm("mov.b64 %0, {%1, %1};" : "=l"(xv2) : "r"(xu));
                    ulonglong2 wA = *reinterpret_cast<const ulonglong2*>(wp + c * CG);
                    ulonglong2 wB = *reinterpret_cast<const ulonglong2*>(wp + c * CG + 4);
                    asm("fma.rn.f32x2 %0, %1, %2, %3;" : "=l"(a0) : "l"(xv2), "l"(wA.x), "l"(a0));
                    asm("fma.rn.f32x2 %0, %1, %2, %3;" : "=l"(a1) : "l"(xv2), "l"(wA.y), "l"(a1));
                    asm("fma.rn.f32x2 %0, %1, %2, %3;" : "=l"(a2) : "l"(xv2), "l"(wB.x), "l"(a2));
                    asm("fma.rn.f32x2 %0, %1, %2, %3;" : "=l"(a3) : "l"(xv2), "l"(wB.y), "l"(a3));
                }
            }
        }
    }

    // ---- Phase 3: cross-warp K reduction ----
    if (chalf == 1 && lane < 28) {
        float* p = &sP[(rowL * 28 + lane) * CG];
        ulonglong2* p2 = reinterpret_cast<ulonglong2*>(p);
        p2[0] = make_ulonglong2(a0, a1);
        p2[1] = make_ulonglong2(a2, a3);
    }
    __syncthreads();

    if (chalf == 0 && lane < 28) {
        const float* p = &sP[(rowL * 28 + lane) * CG];
        float res[8];
        res[0] = __uint_as_float((uint32_t)(a0      )) + p[0] + sC[0];
        res[1] = __uint_as_float((uint32_t)(a0 >> 32)) + p[1] + sC[1];
        res[2] = __uint_as_float((uint32_t)(a1      )) + p[2] + sC[2];
        res[3] = __uint_as_float((uint32_t)(a1 >> 32)) + p[3] + sC[3];
        res[4] = __uint_as_float((uint32_t)(a2      )) + p[4] + sC[4];
        res[5] = __uint_as_float((uint32_t)(a2 >> 32)) + p[5] + sC[5];
        res[6] = __uint_as_float((uint32_t)(a3      )) + p[6] + sC[6];
        res[7] = __uint_as_float((uint32_t)(a3 >> 32)) + p[7] + sC[7];

        const int row = row0 + rowL;
        float* o = out + (((size_t)b * COUT_ + cobase) * H_ + row) * W_ + lane;
        #pragma unroll
        for (int j = 0; j < 8; j++)
            o[(size_t)j * (H_ * W_)] = res[j];
    }
}

extern "C" void kernel_launch(void* const* d_in, const int* in_sizes, int n_in,
                              void* d_out, int out_size)
{
    (void)in_sizes; (void)n_in; (void)out_size;
    const float* x    = (const float*)d_in[0];
    const float* k    = (const float*)d_in[1];
    const float* bias = (const float*)d_in[2];
    const float* dx   = (const float*)d_in[3];
    const float* dw   = (const float*)d_in[4];
    float* out        = (float*)d_out;

    dim3 grid(14, B_, COUT_ / CG);   // 14*8*8 = 896 blocks, 3584 warps
    fused_conv_kernel<<<grid, NTHR>>>(x, k, bias, dx, dw, out);
}

// round 7
// speedup vs baseline: 1.6093x; 1.2948x over previous
#include <cuda_runtime.h>
#include <cstdint>

// out[b,co,h,w] = sum_{kh,kw,cin} xpad[b,cin,h+kh-1,w+kw-1] * (exp(k[kh,kw,cin,co]+5) - delta_w)
//              + sum_r exp(k_r+5) - delta_x * sum_r k_r + bias[co]
// alpha=1 so exp(lse) = sum exp(z); exp(log(x+1)) = x+1; zero-padded lnx
// positions give exp(0)=1 == the (x+1) form at x=0. The -xp*delta_w term is
// an all-ones conv of x folded into W'' = e - delta_w.

#define B_     8
#define CIN_   32
#define H_     28
#define W_     28
#define COUT_  64
#define R_     288   // 3*3*32

constexpr int TR   = 4;    // output rows per block (7 tiles cover 28)
constexpr int CG   = 8;    // couts per block
constexpr int NTHR = 256;  // 8 warps, K-split: warp w handles cin [4w, 4w+4)
constexpr int XR   = TR + 2;                // 6 input rows
constexpr int XROW = 32;                    // padded col width
constexpr int XSZ  = CIN_ * XR * XROW;      // 6144 floats = 24 KB

__global__ void __launch_bounds__(NTHR, 3) fused_conv_kernel(
    const float* __restrict__ x,
    const float* __restrict__ k,
    const float* __restrict__ bias,
    const float* __restrict__ dxp,
    const float* __restrict__ dwp,
    float* __restrict__ out)
{
    __shared__ __align__(16) float sW[R_ * CG];            // 9216 B [r][co_local]
    __shared__ __align__(16) float sX[XSZ];                // 24576 B [cin][6 rows][32 cols]
    __shared__ __align__(16) unsigned long long sP[4 * 16 * 28]; // 14336 B: 4 bufs of f32x2 partials
    __shared__ float redE[CG][32];
    __shared__ float redK[CG][32];
    __shared__ float sC[CG];

    const int tid    = threadIdx.x;
    const int rt     = blockIdx.x;          // 0..6 row tile
    const int b      = blockIdx.y;          // 0..7 batch
    const int cg     = blockIdx.z;          // 0..7 cout group
    const int row0   = rt * TR;
    const int cobase = cg * CG;

    const float dw = dwp[0];
    const float dx = dxp[0];

    // ---- Phase 1a: weight transform (exp) + partial sums for C[co] ----
    {
        const int co  = tid & 7;            // 0..7 local cout
        const int seg = tid >> 3;           // 0..31
        float se = 0.f, sk = 0.f;
        #pragma unroll
        for (int rr = seg; rr < R_; rr += 32) {
            float kv = k[rr * COUT_ + cobase + co];
            float e  = expf(kv + 5.0f);
            sW[rr * CG + co] = e - dw;
            se += e;
            sk += kv;
        }
        redE[co][seg] = se;
        redK[co][seg] = sk;
    }

    // ---- Phase 1b: input tile, rows row0-1..row0+4, cols -1..30, zero pad ----
    {
        const float* xb = x + (size_t)b * (CIN_ * H_ * W_);
        #pragma unroll
        for (int i = 0; i < XSZ / NTHR; i++) {
            int idx = i * NTHR + tid;
            int c   = idx / (XR * XROW);
            int rem = idx - c * (XR * XROW);
            int rr  = rem >> 5;             // 0..5
            int cc  = rem & 31;             // 0..31
            int ir  = row0 - 1 + rr;
            int ic  = cc - 1;
            float v = 0.f;
            if ((unsigned)ir < (unsigned)H_ && (unsigned)ic < (unsigned)W_)
                v = xb[(c * H_ + ir) * W_ + ic];
            sX[idx] = v;
        }
    }
    __syncthreads();

    // ---- Phase 1c: finish C[co] reduction ----
    if (tid < CG) {
        float S = 0.f, K = 0.f;
        #pragma unroll
        for (int i = 0; i < 32; i++) { S += redE[tid][i]; K += redK[tid][i]; }
        sC[tid] = S - dx * K + bias[cobase + tid];
    }

    // ---- Phase 2: main conv. warp w: cin [4w,4w+4), all threads: 4 rows x 8 couts ----
    const int wid  = tid >> 5;
    const int lane = tid & 31;
    const int c0   = wid * 4;

    unsigned long long acc[16];             // [row r][cout-pair j] = acc[r*4+j]
    #pragma unroll
    for (int i = 0; i < 16; i++) acc[i] = 0ull;

    if (lane < 28) {
        #pragma unroll
        for (int kh = 0; kh < 3; kh++) {
            #pragma unroll
            for (int kw = 0; kw < 3; kw++) {
                const float* xp = &sX[c0 * (XR * XROW) + kh * XROW + lane + kw];
                const float* wp = &sW[((kh * 3 + kw) * CIN_ + c0) * CG];
                #pragma unroll
                for (int c = 0; c < 4; c++) {
                    unsigned long long xv[TR];
                    #pragma unroll
                    for (int r = 0; r < TR; r++) {
                        uint32_t xu = __float_as_uint(xp[c * (XR * XROW) + r * XROW]);
                        asm("mov.b64 %0, {%1, %1};" : "=l"(xv[r]) : "r"(xu));
                    }
                    ulonglong2 wA = *reinterpret_cast<const ulonglong2*>(wp + c * CG);
                    ulonglong2 wB = *reinterpret_cast<const ulonglong2*>(wp + c * CG + 4);
                    #pragma unroll
                    for (int r = 0; r < TR; r++) {
                        asm("fma.rn.f32x2 %0, %1, %2, %3;" : "=l"(acc[r*4+0]) : "l"(xv[r]), "l"(wA.x), "l"(acc[r*4+0]));
                        asm("fma.rn.f32x2 %0, %1, %2, %3;" : "=l"(acc[r*4+1]) : "l"(xv[r]), "l"(wA.y), "l"(acc[r*4+1]));
                        asm("fma.rn.f32x2 %0, %1, %2, %3;" : "=l"(acc[r*4+2]) : "l"(xv[r]), "l"(wB.x), "l"(acc[r*4+2]));
                        asm("fma.rn.f32x2 %0, %1, %2, %3;" : "=l"(acc[r*4+3]) : "l"(xv[r]), "l"(wB.y), "l"(acc[r*4+3]));
                    }
                }
            }
        }
    }

    // ---- Phase 3: 8-way K reduction (tree via f32x2 in smem, lane-consecutive) ----
    // stage 1: warps 4..7 store buf[w-4]; warps 0..3 add buf[w]
    if (wid >= 4 && lane < 28) {
        unsigned long long* p = &sP[((wid - 4) * 16) * 28 + lane];
        #pragma unroll
        for (int j = 0; j < 16; j++) p[j * 28] = acc[j];
    }
    __syncthreads();
    if (wid < 4 && lane < 28) {
        const unsigned long long* p = &sP[(wid * 16) * 28 + lane];
        #pragma unroll
        for (int j = 0; j < 16; j++) {
            unsigned long long v = p[j * 28];
            asm("add.rn.f32x2 %0, %1, %2;" : "=l"(acc[j]) : "l"(acc[j]), "l"(v));
        }
    }
    __syncthreads();
    // stage 2: warps 1..3 store buf[w]; warp 0 adds bufs 1..3
    if (wid >= 1 && wid < 4 && lane < 28) {
        unsigned long long* p = &sP[(wid * 16) * 28 + lane];
        #pragma unroll
        for (int j = 0; j < 16; j++) p[j * 28] = acc[j];
    }
    __syncthreads();

    if (wid == 0 && lane < 28) {
        #pragma unroll
        for (int w = 1; w < 4; w++) {
            const unsigned long long* p = &sP[(w * 16) * 28 + lane];
            #pragma unroll
            for (int j = 0; j < 16; j++) {
                unsigned long long v = p[j * 28];
                asm("add.rn.f32x2 %0, %1, %2;" : "=l"(acc[j]) : "l"(acc[j]), "l"(v));
            }
        }

        float* o = out + (((size_t)b * COUT_ + cobase) * H_ + row0) * W_ + lane;
        #pragma unroll
        for (int r = 0; r < TR; r++) {
            #pragma unroll
            for (int j = 0; j < 4; j++) {
                unsigned long long a = acc[r*4+j];
                float lo = __uint_as_float((uint32_t)a)        + sC[2*j];
                float hi = __uint_as_float((uint32_t)(a >> 32)) + sC[2*j+1];
                o[(size_t)(2*j  ) * (H_*W_) + r * W_] = lo;
                o[(size_t)(2*j+1) * (H_*W_) + r * W_] = hi;
            }
        }
    }
}

extern "C" void kernel_launch(void* const* d_in, const int* in_sizes, int n_in,
                              void* d_out, int out_size)
{
    (void)in_sizes; (void)n_in; (void)out_size;
    const float* x    = (const float*)d_in[0];
    const float* k    = (const float*)d_in[1];
    const float* bias = (const float*)d_in[2];
    const float* dx   = (const float*)d_in[3];
    const float* dw   = (const float*)d_in[4];
    float* out        = (float*)d_out;

    dim3 grid(7, B_, COUT_ / CG);   // 7*8*8 = 448 blocks x 8 warps = 3584 warps
    fused_conv_kernel<<<grid, NTHR>>>(x, k, bias, dx, dw, out);
}